// round 14
// baseline (speedup 1.0000x reference)
#include <cuda_runtime.h>
#include <cuda_fp16.h>
#include <cstdint>

// ---------------------------------------------------------------------------
// GAT layer, sm_103 base ISA. Warp-specialized producer/consumer pipeline.
// Round 14: adjacency loaded DIRECTLY into registers (16x LDG.128, MLP=16,
// prefetched one tile ahead) — no adj smem staging, no bank conflicts, no
// cp.async group juggling (B tile only). 4-stage P/B ring.
//  - separable exp (R13): P = sel(E1,E1s)*sel(E2,E2s), no MUFU in hot loop.
//  - persistent k_attn: 148 CTAs, 1024 static units, red.global.add flush.
// ---------------------------------------------------------------------------

#define NROWS 8192
#define FDIM  128
#define BM    128
#define BN    64
#define SHIFT 7.0f
#define NSTAGE 4
#define JTILES_U 8                 // tiles per unit
#define NUNITS  1024               // 64 i-tiles * 16 j-chunks
#define ATTN_GRID 148

// ---- scratch (device globals; no allocation allowed) ----
__device__ float  g_e1 [NROWS];    // exp(s1 - SHIFT)
__device__ float  g_e1s[NROWS];    // exp(0.01*s1 - SHIFT)
__device__ float  g_t1 [NROWS];    // exp(-s1)
__device__ float  g_e2 [NROWS];    // exp(s2)
__device__ float  g_e2s[NROWS];    // exp(0.01*s2)
__device__ __half g_hT_hi[(size_t)FDIM * NROWS];   // [c][j]
__device__ float  g_num[(size_t)NROWS * FDIM];
__device__ float  g_den[NROWS];

// ---------------------------------------------------------------------------
static __device__ __forceinline__ uint32_t smem_u32(const void* p) {
    uint32_t a;
    asm("{ .reg .u64 t; cvta.to.shared.u64 t, %1; cvt.u32.u64 %0, t; }"
        : "=r"(a) : "l"(p));
    return a;
}

static __device__ __forceinline__ void ldm_x4(uint32_t* r, uint32_t addr) {
    asm volatile("ldmatrix.sync.aligned.m8n8.x4.shared.b16 {%0,%1,%2,%3}, [%4];"
                 : "=r"(r[0]), "=r"(r[1]), "=r"(r[2]), "=r"(r[3]) : "r"(addr));
}

static __device__ __forceinline__ void mma16816(float* d, const uint32_t* a,
                                                uint32_t b0, uint32_t b1) {
    asm volatile(
        "mma.sync.aligned.m16n8k16.row.col.f32.f16.f16.f32 "
        "{%0,%1,%2,%3}, {%4,%5,%6,%7}, {%8,%9}, {%0,%1,%2,%3};"
        : "+f"(d[0]), "+f"(d[1]), "+f"(d[2]), "+f"(d[3])
        : "r"(a[0]), "r"(a[1]), "r"(a[2]), "r"(a[3]), "r"(b0), "r"(b1));
}

static __device__ __forceinline__ uint32_t pack_h2f(float lo, float hi) {
    uint32_t r;
    asm("cvt.rn.f16x2.f32 %0, %1, %2;" : "=r"(r) : "f"(hi), "f"(lo));
    return r;
}

#define RED_ADD(ptr, v) \
    asm volatile("red.global.add.f32 [%0], %1;" :: "l"(ptr), "f"(v) : "memory")

// A-operand ldmatrix address: tile m16k16 at (m0, ks), 128B rows, chunk-XOR swizzle
static __device__ __forceinline__ uint32_t a_addr(uint32_t base, int m0, int ks, int lane) {
    int q = lane >> 3, row = lane & 7;
    int rr = m0 + ((q & 1) << 3) + row;
    int kc = ks * 2 + (q >> 1);
    return base + rr * 128 + ((kc ^ (rr & 7)) << 4);
}
// B-operand ldmatrix address: tile n16k16 at (n0, ks); B stored [n][k] rows
static __device__ __forceinline__ uint32_t b_addr(uint32_t base, int n0, int ks, int lane) {
    int q = lane >> 3, row = lane & 7;
    int nn = n0 + ((q >> 1) << 3) + row;
    int kc = ks * 2 + (q & 1);
    return base + nn * 128 + ((kc ^ (nn & 7)) << 4);
}

static __device__ __forceinline__ void mbar_init(uint32_t m, uint32_t cnt) {
    asm volatile("mbarrier.init.shared.b64 [%0], %1;" :: "r"(m), "r"(cnt) : "memory");
}
static __device__ __forceinline__ void mbar_arrive(uint32_t m) {
    asm volatile("mbarrier.arrive.shared.b64 _, [%0];" :: "r"(m) : "memory");
}
static __device__ __forceinline__ void mbar_wait(uint32_t m, uint32_t parity) {
    uint32_t done;
    asm volatile(
        "{\n\t.reg .pred p;\n\t"
        "mbarrier.try_wait.parity.acquire.cta.shared::cta.b64 p, [%1], %2;\n\t"
        "selp.b32 %0, 1, 0, p;\n\t}"
        : "=r"(done) : "r"(m), "r"(parity) : "memory");
    if (!done) {
        asm volatile(
            "{\n\t.reg .pred P1;\n\t"
            "WL_%=:\n\t"
            "mbarrier.try_wait.parity.acquire.cta.shared::cta.b64 P1, [%0], %1, 0x989680;\n\t"
            "@P1 bra.uni WD_%=;\n\t"
            "bra.uni WL_%=;\n\t"
            "WD_%=:\n\t}"
            :: "r"(m), "r"(parity) : "memory");
    }
}

static __device__ __forceinline__ void cp_async16(uint32_t dst, const void* src) {
    asm volatile("cp.async.cg.shared.global [%0], [%1], 16;"
                 :: "r"(dst), "l"(src) : "memory");
}
static __device__ __forceinline__ void cp_commit()  { asm volatile("cp.async.commit_group;" ::: "memory"); }
static __device__ __forceinline__ void cp_wait0()   { asm volatile("cp.async.wait_group 0;" ::: "memory"); }

// ---------------------------------------------------------------------------
// Kernel 0: zero g_num / g_den (required every launch; REDG accumulates)
// ---------------------------------------------------------------------------
#define NUM4 ((NROWS * FDIM) / 4)
#define DEN4 (NROWS / 4)

__global__ void k_zero() {
    int idx = blockIdx.x * 256 + threadIdx.x;
    float4 z = make_float4(0.f, 0.f, 0.f, 0.f);
    if (idx < NUM4) ((float4*)g_num)[idx] = z;
    else if (idx - NUM4 < DEN4) ((float4*)g_den)[idx - NUM4] = z;
}

// ---------------------------------------------------------------------------
// Kernel 1: h = X@W ; exp-separated softmax tables ; transposed fp16 h
// ---------------------------------------------------------------------------
#define PBM 64
#define HS_PITCH 133
#define PREP_SMEM ((16384 + PBM * HS_PITCH) * 4)

__global__ __launch_bounds__(512, 1)
void k_prep(const float* __restrict__ inp, const float* __restrict__ W,
            const float* __restrict__ a) {
    extern __shared__ float smf[];
    float* Ws = smf;                    // [k=128][c=128], natural layout
    float* hs = smf + 16384;            // [64][HS_PITCH]

    const int t  = threadIdx.x;
    const int i0 = blockIdx.x * PBM;

    for (int idx = t; idx < 16384; idx += 512) Ws[idx] = W[idx];
    __syncthreads();

    const int c4 = t & 31;    // column group (lane)
    const int rb = t >> 5;    // row block (uniform per warp)
    const float* irow = inp + (size_t)(i0 + rb * 4) * FDIM;

    float acc[4][4];
#pragma unroll
    for (int r = 0; r < 4; r++)
#pragma unroll
        for (int cc = 0; cc < 4; cc++) acc[r][cc] = 0.0f;

    for (int k4 = 0; k4 < 32; k4++) {
        float4 iv[4];
#pragma unroll
        for (int r = 0; r < 4; r++)
            iv[r] = *(const float4*)&irow[r * FDIM + k4 * 4];
        float4 wv[4];
#pragma unroll
        for (int kk = 0; kk < 4; kk++)
            wv[kk] = *(const float4*)&Ws[(k4 * 4 + kk) * 128 + c4 * 4];
#pragma unroll
        for (int r = 0; r < 4; r++) {
            float4 v = iv[r];
            acc[r][0] = fmaf(v.x, wv[0].x, fmaf(v.y, wv[1].x,
                        fmaf(v.z, wv[2].x, fmaf(v.w, wv[3].x, acc[r][0]))));
            acc[r][1] = fmaf(v.x, wv[0].y, fmaf(v.y, wv[1].y,
                        fmaf(v.z, wv[2].y, fmaf(v.w, wv[3].y, acc[r][1]))));
            acc[r][2] = fmaf(v.x, wv[0].z, fmaf(v.y, wv[1].z,
                        fmaf(v.z, wv[2].z, fmaf(v.w, wv[3].z, acc[r][2]))));
            acc[r][3] = fmaf(v.x, wv[0].w, fmaf(v.y, wv[1].w,
                        fmaf(v.z, wv[2].w, fmaf(v.w, wv[3].w, acc[r][3]))));
        }
    }
#pragma unroll
    for (int r = 0; r < 4; r++)
#pragma unroll
        for (int cc = 0; cc < 4; cc++)
            hs[(rb * 4 + r) * HS_PITCH + c4 * 4 + cc] = acc[r][cc];
    __syncthreads();

    if (t < PBM) {
        float s1 = 0.0f, s2 = 0.0f;
        for (int cc = 0; cc < 128; cc++) {
            float hv = hs[t * HS_PITCH + cc];
            s1 += hv * a[cc];
            s2 += hv * a[128 + cc];
        }
        const int gi = i0 + t;
        g_e1 [gi] = __expf(s1 - SHIFT);
        g_e1s[gi] = __expf(0.01f * s1 - SHIFT);
        g_t1 [gi] = __expf(-s1);
        g_e2 [gi] = __expf(s2);
        g_e2s[gi] = __expf(0.01f * s2);
    }

    const int ii = t & 63;
    const int c0 = t >> 6;    // 0..7
    for (int cc = c0; cc < 128; cc += 8)
        g_hT_hi[(size_t)cc * NROWS + i0 + ii] =
            __float2half_rn(hs[ii * HS_PITCH + cc]);
}

// ---------------------------------------------------------------------------
// Kernel 2: persistent warp-specialized fused masked-softmax + P@h
// smem: 4 stages x { Ph 16KB | Bh 16KB } + mbars. adj lives in registers.
// ---------------------------------------------------------------------------
#define ST_SZ   32768u
#define OFF_PH  0u
#define OFF_BH  16384u
#define SM_MB   131072u   // full[0..3], empty[0..3] (8B each)
#define ATTN_SMEM 131136u

__global__ __launch_bounds__(256, 1)
void k_attn(const int* __restrict__ adj) {
    extern __shared__ char smem[];
    const uint32_t sb = smem_u32(smem);

    const int t    = threadIdx.x;
    const int lane = t & 31;
    const int w    = t >> 5;

    if (t == 0) {
#pragma unroll
        for (int s = 0; s < NSTAGE; s++) {
            mbar_init(sb + SM_MB + s * 8, 128);               // full[s]
            mbar_init(sb + SM_MB + (NSTAGE + s) * 8, 128);    // empty[s]
        }
    }
    __syncthreads();

    int st = 0;

    if (w >= 4) {
        // ------------------------- producers (warps 4-7) -------------------
        const int pw   = w - 4;
        const int rsub = lane >> 3;     // 0..3 : row-in-group
        const int jc   = lane & 7;      // 0..7 : 8-col group within BN=64
        int ph_par = 1;

        float dacc[8];
#pragma unroll
        for (int g = 0; g < 8; g++) dacc[g] = 0.0f;

        // adj register buffer: Ar[2g],Ar[2g+1] = row g, cols jc*8..+7
        int4 Ar[16];

        // prologue: load adj for the very first tile of this CTA
        {
            const int u0  = blockIdx.x;
            const int fi0 = (u0 & 63) * BM;
            const int fj0 = (u0 >> 6) * (JTILES_U * BN);
#pragma unroll
            for (int g = 0; g < 8; g++) {
                const int4* src = (const int4*)(adj +
                    (size_t)(fi0 + pw * 32 + g * 4 + rsub) * NROWS + fj0 + jc * 8);
                Ar[2 * g]     = src[0];
                Ar[2 * g + 1] = src[1];
            }
        }

        for (int u = blockIdx.x; u < NUNITS; u += gridDim.x) {
            const int i0  = (u & 63) * BM;
            const int j0b = (u >> 6) * (JTILES_U * BN);

            // per-unit row constants (exp-separated softmax tables)
            float Av[8], As[8], Tv[8];
#pragma unroll
            for (int g = 0; g < 8; g++) {
                const int ri = i0 + pw * 32 + g * 4 + rsub;
                Av[g] = g_e1[ri];
                As[g] = g_e1s[ri];
                Tv[g] = g_t1[ri];
            }

            for (int tile = 0; tile < JTILES_U; ++tile) {
                const int j0 = j0b + tile * BN;
                mbar_wait(sb + SM_MB + (NSTAGE + st) * 8, ph_par);

                // async-load B tile (h^T fp16), swizzled (conflict-free)
                const uint32_t bh = sb + st * ST_SZ + OFF_BH;
#pragma unroll
                for (int cc = 0; cc < 8; cc++) {
                    const int cr = pw * 32 + cc * 4 + rsub;
                    const uint32_t dst = cr * 128 + ((jc ^ (cr & 7)) << 4);
                    cp_async16(bh + dst,
                               (const char*)g_hT_hi + ((size_t)cr * NROWS + j0 + jc * 8) * 2);
                }
                cp_commit();                               // B_t (only group)

                // compute P tile (fp16, swizzled) from adj REGISTERS
                char* phb = smem + st * ST_SZ + OFF_PH;

                const float4* e2p  = (const float4*)(g_e2  + j0 + jc * 8);
                const float4* e2sp = (const float4*)(g_e2s + j0 + jc * 8);
                const float4 B0 = e2p[0],  B1 = e2p[1];
                const float4 C0 = e2sp[0], C1 = e2sp[1];
                const float Bv[8] = {B0.x, B0.y, B0.z, B0.w, B1.x, B1.y, B1.z, B1.w};
                const float Bs[8] = {C0.x, C0.y, C0.z, C0.w, C1.x, C1.y, C1.z, C1.w};

#pragma unroll
                for (int g = 0; g < 8; g++) {
                    const int r = pw * 32 + g * 4 + rsub;
                    const int4 A0 = Ar[2 * g];
                    const int4 A1 = Ar[2 * g + 1];
                    const int av[8] = {A0.x, A0.y, A0.z, A0.w, A1.x, A1.y, A1.z, A1.w};
                    const float Ag = Av[g], Asg = As[g], Tg = Tv[g];
                    float pv[8];
#pragma unroll
                    for (int uu = 0; uu < 8; uu++) {
                        const bool pos = Bv[uu] > Tg;          // s1+s2 >= 0 ?
                        float sa  = pos ? Ag : Asg;
                        float sbv = pos ? Bv[uu] : Bs[uu];
                        float v = sa * sbv;
                        v = (av[uu] > 0) ? v : 0.0f;
                        dacc[g] += v;
                        pv[uu] = v;
                    }
                    uint4 HH = make_uint4(pack_h2f(pv[0], pv[1]), pack_h2f(pv[2], pv[3]),
                                          pack_h2f(pv[4], pv[5]), pack_h2f(pv[6], pv[7]));
                    *(uint4*)(phb + r * 128 + ((jc ^ (r & 7)) << 4)) = HH;
                }

                // prefetch next tile's adj into the (now free) registers
                const bool have_next =
                    !(tile == JTILES_U - 1 && u + (int)gridDim.x >= NUNITS);
                if (have_next) {
                    const int*  nbase;
                    if (tile < JTILES_U - 1) {
                        nbase = adj + (size_t)i0 * NROWS + j0 + BN;
                    } else {
                        const int nu = u + gridDim.x;
                        nbase = adj + (size_t)((nu & 63) * BM) * NROWS
                                    + (nu >> 6) * (JTILES_U * BN);
                    }
#pragma unroll
                    for (int g = 0; g < 8; g++) {
                        const int4* src = (const int4*)(nbase +
                            (size_t)(pw * 32 + g * 4 + rsub) * NROWS + jc * 8);
                        Ar[2 * g]     = src[0];
                        Ar[2 * g + 1] = src[1];
                    }
                }

                cp_wait0();                          // B tile landed
                mbar_arrive(sb + SM_MB + st * 8);    // full[st]

                if (++st == NSTAGE) { st = 0; ph_par ^= 1; }
            }

            // unit flush: reduce dacc over the 8 jc lanes, red.add, reset
#pragma unroll
            for (int d = 1; d < 8; d <<= 1)
#pragma unroll
                for (int g = 0; g < 8; g++)
                    dacc[g] += __shfl_xor_sync(0xffffffffu, dacc[g], d);
            if (jc == 0) {
#pragma unroll
                for (int g = 0; g < 8; g++)
                    RED_ADD(&g_den[i0 + pw * 32 + g * 4 + rsub], dacc[g]);
            }
#pragma unroll
            for (int g = 0; g < 8; g++) dacc[g] = 0.0f;
        }
    } else {
        // ------------------------- consumers (warps 0-3) -------------------
        const int m0 = w * 32;
        int ph_par = 0;

        float acc[2][16][4];
#pragma unroll
        for (int mt = 0; mt < 2; mt++)
#pragma unroll
            for (int nt = 0; nt < 16; nt++)
#pragma unroll
                for (int uu = 0; uu < 4; uu++) acc[mt][nt][uu] = 0.0f;

        for (int u = blockIdx.x; u < NUNITS; u += gridDim.x) {
            const int i0 = (u & 63) * BM;

            for (int tile = 0; tile < JTILES_U; ++tile) {
                mbar_wait(sb + SM_MB + st * 8, ph_par);

                const uint32_t ph = sb + st * ST_SZ + OFF_PH;
                const uint32_t bh = sb + st * ST_SZ + OFF_BH;

#pragma unroll
                for (int ks = 0; ks < 4; ks++) {
                    uint32_t a0[4], a1[4];
                    ldm_x4(a0, a_addr(ph, m0,      ks, lane));
                    ldm_x4(a1, a_addr(ph, m0 + 16, ks, lane));
#pragma unroll
                    for (int n16 = 0; n16 < 8; n16++) {
                        uint32_t B0[4];
                        ldm_x4(B0, b_addr(bh, n16 * 16, ks, lane));
                        mma16816(acc[0][2 * n16],     a0, B0[0], B0[1]);
                        mma16816(acc[0][2 * n16 + 1], a0, B0[2], B0[3]);
                        mma16816(acc[1][2 * n16],     a1, B0[0], B0[1]);
                        mma16816(acc[1][2 * n16 + 1], a1, B0[2], B0[3]);
                    }
                }

                mbar_arrive(sb + SM_MB + (NSTAGE + st) * 8);  // empty[st]
                if (++st == NSTAGE) { st = 0; ph_par ^= 1; }
            }

            // unit flush: red.add numerator partials, reset accumulators
#pragma unroll
            for (int mt = 0; mt < 2; mt++) {
                const int row = i0 + m0 + mt * 16 + (lane >> 2);
#pragma unroll
                for (int nt = 0; nt < 16; nt++) {
                    const int col = nt * 8 + (lane & 3) * 2;
                    float* b0 = g_num + (size_t)row * FDIM + col;
                    float* b1 = g_num + (size_t)(row + 8) * FDIM + col;
                    RED_ADD(b0,     acc[mt][nt][0]);
                    RED_ADD(b0 + 1, acc[mt][nt][1]);
                    RED_ADD(b1,     acc[mt][nt][2]);
                    RED_ADD(b1 + 1, acc[mt][nt][3]);
                    acc[mt][nt][0] = 0.0f; acc[mt][nt][1] = 0.0f;
                    acc[mt][nt][2] = 0.0f; acc[mt][nt][3] = 0.0f;
                }
            }
        }
    }
}

// ---------------------------------------------------------------------------
// Kernel 3: out = num / den, float4-vectorized
// ---------------------------------------------------------------------------
__global__ void k_combine(float* __restrict__ out) {
    int idx  = blockIdx.x * 256 + threadIdx.x;
    int base = idx * 4;
    int i    = base >> 7;
    float inv = __frcp_rn(g_den[i]);
    float4 n = *(const float4*)&g_num[base];
    float4 o;
    o.x = n.x * inv;
    o.y = n.y * inv;
    o.z = n.z * inv;
    o.w = n.w * inv;
    *(float4*)&out[base] = o;
}

// ---------------------------------------------------------------------------
extern "C" void kernel_launch(void* const* d_in, const int* in_sizes, int n_in,
                              void* d_out, int out_size) {
    const float* inp = (const float*)d_in[0];
    const int*   adj = (const int*)d_in[1];
    const float* W   = (const float*)d_in[2];
    const float* a   = (const float*)d_in[3];
    float* out = (float*)d_out;

    cudaFuncSetAttribute(k_prep, cudaFuncAttributeMaxDynamicSharedMemorySize, PREP_SMEM);
    cudaFuncSetAttribute(k_attn, cudaFuncAttributeMaxDynamicSharedMemorySize, ATTN_SMEM);

    k_zero<<<(NUM4 + DEN4 + 255) / 256, 256>>>();
    k_prep<<<NROWS / PBM, 512, PREP_SMEM>>>(inp, W, a);
    k_attn<<<ATTN_GRID, 256, ATTN_SMEM>>>(adj);
    k_combine<<<(NROWS * FDIM) / 1024, 256>>>(out);
}

// round 15
// speedup vs baseline: 1.0629x; 1.0629x over previous
#include <cuda_runtime.h>
#include <cuda_fp16.h>
#include <cstdint>

// ---------------------------------------------------------------------------
// GAT layer, sm_103 base ISA. Warp-specialized producer/consumer (R8 skeleton)
// Round 15:
//  - consumer warp tiles 64Mx64N: 32 ldmatrix/tile/warp (was 40) -> less
//    smem-crossbar traffic alongside the tensor stream
//  - separable exp producer (R13 math): no MUFU in hot loop
//  - otherwise exactly R8: JSPLIT=2, 128 CTAs, adj smem double-buffer,
//    direct writeout, 3-stage P/B ring
// ---------------------------------------------------------------------------

#define NROWS 8192
#define FDIM  128
#define BM    128
#define BN    64
#define JSPLIT 2
#define JTILES ((NROWS / JSPLIT) / BN)   // 64
#define SHIFT 7.0f
#define NSTAGE 3

// ---- scratch (device globals; no allocation allowed) ----
__device__ float  g_e1 [NROWS];    // exp(s1 - SHIFT)
__device__ float  g_e1s[NROWS];    // exp(0.01*s1 - SHIFT)
__device__ float  g_t1 [NROWS];    // exp(-s1)
__device__ float  g_e2 [NROWS];    // exp(s2)
__device__ float  g_e2s[NROWS];    // exp(0.01*s2)
__device__ __half g_hT_hi[(size_t)FDIM * NROWS];   // [c][j]
__device__ float  g_num[JSPLIT][(size_t)NROWS * FDIM];
__device__ float  g_den[JSPLIT][NROWS];

// ---------------------------------------------------------------------------
static __device__ __forceinline__ uint32_t smem_u32(const void* p) {
    uint32_t a;
    asm("{ .reg .u64 t; cvta.to.shared.u64 t, %1; cvt.u32.u64 %0, t; }"
        : "=r"(a) : "l"(p));
    return a;
}

static __device__ __forceinline__ void ldm_x4(uint32_t* r, uint32_t addr) {
    asm volatile("ldmatrix.sync.aligned.m8n8.x4.shared.b16 {%0,%1,%2,%3}, [%4];"
                 : "=r"(r[0]), "=r"(r[1]), "=r"(r[2]), "=r"(r[3]) : "r"(addr));
}

static __device__ __forceinline__ void mma16816(float* d, const uint32_t* a,
                                                uint32_t b0, uint32_t b1) {
    asm volatile(
        "mma.sync.aligned.m16n8k16.row.col.f32.f16.f16.f32 "
        "{%0,%1,%2,%3}, {%4,%5,%6,%7}, {%8,%9}, {%0,%1,%2,%3};"
        : "+f"(d[0]), "+f"(d[1]), "+f"(d[2]), "+f"(d[3])
        : "r"(a[0]), "r"(a[1]), "r"(a[2]), "r"(a[3]), "r"(b0), "r"(b1));
}

static __device__ __forceinline__ uint32_t pack_h2f(float lo, float hi) {
    uint32_t r;
    asm("cvt.rn.f16x2.f32 %0, %1, %2;" : "=r"(r) : "f"(hi), "f"(lo));
    return r;
}

// A-operand ldmatrix address: tile m16k16 at (m0, ks), 128B rows, chunk-XOR swizzle
static __device__ __forceinline__ uint32_t a_addr(uint32_t base, int m0, int ks, int lane) {
    int q = lane >> 3, row = lane & 7;
    int rr = m0 + ((q & 1) << 3) + row;
    int kc = ks * 2 + (q >> 1);
    return base + rr * 128 + ((kc ^ (rr & 7)) << 4);
}
// B-operand ldmatrix address: tile n16k16 at (n0, ks); B stored [n][k] rows
static __device__ __forceinline__ uint32_t b_addr(uint32_t base, int n0, int ks, int lane) {
    int q = lane >> 3, row = lane & 7;
    int nn = n0 + ((q >> 1) << 3) + row;
    int kc = ks * 2 + (q & 1);
    return base + nn * 128 + ((kc ^ (nn & 7)) << 4);
}

static __device__ __forceinline__ void mbar_init(uint32_t m, uint32_t cnt) {
    asm volatile("mbarrier.init.shared.b64 [%0], %1;" :: "r"(m), "r"(cnt) : "memory");
}
static __device__ __forceinline__ void mbar_arrive(uint32_t m) {
    asm volatile("mbarrier.arrive.shared.b64 _, [%0];" :: "r"(m) : "memory");
}
static __device__ __forceinline__ void mbar_wait(uint32_t m, uint32_t parity) {
    uint32_t done;
    asm volatile(
        "{\n\t.reg .pred p;\n\t"
        "mbarrier.try_wait.parity.acquire.cta.shared::cta.b64 p, [%1], %2;\n\t"
        "selp.b32 %0, 1, 0, p;\n\t}"
        : "=r"(done) : "r"(m), "r"(parity) : "memory");
    if (!done) {
        asm volatile(
            "{\n\t.reg .pred P1;\n\t"
            "WL_%=:\n\t"
            "mbarrier.try_wait.parity.acquire.cta.shared::cta.b64 P1, [%0], %1, 0x989680;\n\t"
            "@P1 bra.uni WD_%=;\n\t"
            "bra.uni WL_%=;\n\t"
            "WD_%=:\n\t}"
            :: "r"(m), "r"(parity) : "memory");
    }
}

static __device__ __forceinline__ void cp_async16(uint32_t dst, const void* src) {
    asm volatile("cp.async.cg.shared.global [%0], [%1], 16;"
                 :: "r"(dst), "l"(src) : "memory");
}
static __device__ __forceinline__ void cp_commit()  { asm volatile("cp.async.commit_group;" ::: "memory"); }
static __device__ __forceinline__ void cp_wait0()   { asm volatile("cp.async.wait_group 0;" ::: "memory"); }
static __device__ __forceinline__ void cp_wait1()   { asm volatile("cp.async.wait_group 1;" ::: "memory"); }
static __device__ __forceinline__ void cp_wait2()   { asm volatile("cp.async.wait_group 2;" ::: "memory"); }

// ---------------------------------------------------------------------------
// Kernel 1: h = X@W ; exp-separated softmax tables ; transposed fp16 h
// ---------------------------------------------------------------------------
#define PBM 64
#define HS_PITCH 133
#define PREP_SMEM ((16384 + PBM * HS_PITCH) * 4)

__global__ __launch_bounds__(512, 1)
void k_prep(const float* __restrict__ inp, const float* __restrict__ W,
            const float* __restrict__ a) {
    extern __shared__ float smf[];
    float* Ws = smf;                    // [k=128][c=128], natural layout
    float* hs = smf + 16384;            // [64][HS_PITCH]

    const int t  = threadIdx.x;
    const int i0 = blockIdx.x * PBM;

    for (int idx = t; idx < 16384; idx += 512) Ws[idx] = W[idx];
    __syncthreads();

    const int c4 = t & 31;    // column group (lane)
    const int rb = t >> 5;    // row block (uniform per warp)
    const float* irow = inp + (size_t)(i0 + rb * 4) * FDIM;

    float acc[4][4];
#pragma unroll
    for (int r = 0; r < 4; r++)
#pragma unroll
        for (int cc = 0; cc < 4; cc++) acc[r][cc] = 0.0f;

    for (int k4 = 0; k4 < 32; k4++) {
        float4 iv[4];
#pragma unroll
        for (int r = 0; r < 4; r++)
            iv[r] = *(const float4*)&irow[r * FDIM + k4 * 4];
        float4 wv[4];
#pragma unroll
        for (int kk = 0; kk < 4; kk++)
            wv[kk] = *(const float4*)&Ws[(k4 * 4 + kk) * 128 + c4 * 4];
#pragma unroll
        for (int r = 0; r < 4; r++) {
            float4 v = iv[r];
            acc[r][0] = fmaf(v.x, wv[0].x, fmaf(v.y, wv[1].x,
                        fmaf(v.z, wv[2].x, fmaf(v.w, wv[3].x, acc[r][0]))));
            acc[r][1] = fmaf(v.x, wv[0].y, fmaf(v.y, wv[1].y,
                        fmaf(v.z, wv[2].y, fmaf(v.w, wv[3].y, acc[r][1]))));
            acc[r][2] = fmaf(v.x, wv[0].z, fmaf(v.y, wv[1].z,
                        fmaf(v.z, wv[2].z, fmaf(v.w, wv[3].z, acc[r][2]))));
            acc[r][3] = fmaf(v.x, wv[0].w, fmaf(v.y, wv[1].w,
                        fmaf(v.z, wv[2].w, fmaf(v.w, wv[3].w, acc[r][3]))));
        }
    }
#pragma unroll
    for (int r = 0; r < 4; r++)
#pragma unroll
        for (int cc = 0; cc < 4; cc++)
            hs[(rb * 4 + r) * HS_PITCH + c4 * 4 + cc] = acc[r][cc];
    __syncthreads();

    if (t < PBM) {
        float s1 = 0.0f, s2 = 0.0f;
        for (int cc = 0; cc < 128; cc++) {
            float hv = hs[t * HS_PITCH + cc];
            s1 += hv * a[cc];
            s2 += hv * a[128 + cc];
        }
        const int gi = i0 + t;
        g_e1 [gi] = __expf(s1 - SHIFT);
        g_e1s[gi] = __expf(0.01f * s1 - SHIFT);
        g_t1 [gi] = __expf(-s1);
        g_e2 [gi] = __expf(s2);
        g_e2s[gi] = __expf(0.01f * s2);
    }

    const int ii = t & 63;
    const int c0 = t >> 6;    // 0..7
    for (int cc = c0; cc < 128; cc += 8)
        g_hT_hi[(size_t)cc * NROWS + i0 + ii] =
            __float2half_rn(hs[ii * HS_PITCH + cc]);
}

// ---------------------------------------------------------------------------
// Kernel 2: warp-specialized fused masked-softmax + P@h  (R8 skeleton)
// smem: 3 stages x { Ph 16KB | Bh 16KB } + 2 x 32KB adj buffers + mbars
// ---------------------------------------------------------------------------
#define ST_SZ   32768u
#define OFF_PH  0u
#define OFF_BH  16384u
#define SM_ADJ  98304u    // 2 x 32768
#define SM_MB   163840u   // full[0..2], empty[0..2] (8B each)
#define ATTN_SMEM 163904u

__global__ __launch_bounds__(256, 1)
void k_attn(const int* __restrict__ adj) {
    extern __shared__ char smem[];
    const uint32_t sb = smem_u32(smem);

    const int t    = threadIdx.x;
    const int lane = t & 31;
    const int w    = t >> 5;
    const int i0   = blockIdx.x * BM;
    const int js   = blockIdx.y;
    const int jbeg = js * (NROWS / JSPLIT);

    if (t == 0) {
#pragma unroll
        for (int s = 0; s < NSTAGE; s++) {
            mbar_init(sb + SM_MB + s * 8, 128);               // full[s]
            mbar_init(sb + SM_MB + (NSTAGE + s) * 8, 128);    // empty[s]
        }
    }
    __syncthreads();

    int st = 0;

    if (w >= 4) {
        // ------------------------- producers (warps 4-7) -------------------
        const int p    = t - 128;       // 0..127
        const int pw   = w - 4;
        const int rsub = lane >> 3;     // 0..3 : row-in-group
        const int jc   = lane & 7;      // 0..7 : 16B chunk within 128B row
        int ph_par = 1;

        const int*   myrow = adj + (size_t)(i0 + p) * NROWS + jbeg;
        const uint32_t adst = sb + SM_ADJ + p * 256;  // own row slot (both bufs)

        float dacc[8];
#pragma unroll
        for (int g = 0; g < 8; g++) dacc[g] = 0.0f;

        // per-row constants (exp-separated softmax tables), fixed i0 per CTA
        float Av[8], As[8], Tv[8];
#pragma unroll
        for (int g = 0; g < 8; g++) {
            const int ri = i0 + pw * 32 + g * 4 + rsub;
            Av[g] = g_e1[ri];
            As[g] = g_e1s[ri];
            Tv[g] = g_t1[ri];
        }

        // preload adj tile 0 into adj buffer 0
#pragma unroll
        for (int q = 0; q < 16; q++)
            cp_async16(adst + q * 16, myrow + q * 4);
        cp_commit();                                   // group A0

        for (int tile = 0; tile < JTILES; ++tile) {
            const int j0 = jbeg + tile * BN;
            mbar_wait(sb + SM_MB + (NSTAGE + st) * 8, ph_par);

            // async-load B tile (h^T fp16), swizzled
            const uint32_t bh = sb + st * ST_SZ + OFF_BH;
#pragma unroll
            for (int cc = 0; cc < 8; cc++) {
                const int cr = pw * 32 + cc * 4 + rsub;
                const uint32_t dst = cr * 128 + ((jc ^ (cr & 7)) << 4);
                cp_async16(bh + dst,
                           (const char*)g_hT_hi + ((size_t)cr * NROWS + j0 + jc * 8) * 2);
            }
            cp_commit();                               // group B_t

            // prefetch adj tile t+1 into the other adj buffer
            const int last = (tile == JTILES - 1);
            if (!last) {
                const int* src = myrow + (tile + 1) * BN;
                const uint32_t d2 = adst + (((tile + 1) & 1) * 32768);
#pragma unroll
                for (int q = 0; q < 16; q++)
                    cp_async16(d2 + q * 16, src + q * 4);
                cp_commit();                           // group A_{t+1}
            }

            // wait for adj(t):  pending = [A_t, B_t, (A_{t+1})]
            if (!last) cp_wait2(); else cp_wait1();

            // compute P tile (fp16, swizzled) from smem adj — separable exp
            char* phb = smem + st * ST_SZ + OFF_PH;
            const char* ab = smem + SM_ADJ + (tile & 1) * 32768;

            const float4* e2p  = (const float4*)(g_e2  + j0 + jc * 8);
            const float4* e2sp = (const float4*)(g_e2s + j0 + jc * 8);
            const float4 B0 = e2p[0],  B1 = e2p[1];
            const float4 C0 = e2sp[0], C1 = e2sp[1];
            const float Bv[8] = {B0.x, B0.y, B0.z, B0.w, B1.x, B1.y, B1.z, B1.w};
            const float Bs[8] = {C0.x, C0.y, C0.z, C0.w, C1.x, C1.y, C1.z, C1.w};

#pragma unroll
            for (int g = 0; g < 8; g++) {
                const int r = pw * 32 + g * 4 + rsub;
                const int4 A0 = *(const int4*)(ab + r * 256 + jc * 32);
                const int4 A1 = *(const int4*)(ab + r * 256 + jc * 32 + 16);
                const int av[8] = {A0.x, A0.y, A0.z, A0.w, A1.x, A1.y, A1.z, A1.w};
                const float Ag = Av[g], Asg = As[g], Tg = Tv[g];
                float pv[8];
#pragma unroll
                for (int u = 0; u < 8; u++) {
                    const bool pos = Bv[u] > Tg;           // s1+s2 >= 0 ?
                    float sa  = pos ? Ag : Asg;
                    float sbv = pos ? Bv[u] : Bs[u];
                    float v = sa * sbv;
                    v = (av[u] > 0) ? v : 0.0f;
                    dacc[g] += v;
                    pv[u] = v;
                }
                uint4 HH = make_uint4(pack_h2f(pv[0], pv[1]), pack_h2f(pv[2], pv[3]),
                                      pack_h2f(pv[4], pv[5]), pack_h2f(pv[6], pv[7]));
                *(uint4*)(phb + r * 128 + ((jc ^ (r & 7)) << 4)) = HH;
            }

            // wait for Bh(t), leave adj(t+1) in flight
            if (!last) cp_wait1(); else cp_wait0();
            mbar_arrive(sb + SM_MB + st * 8);   // full[st]

            if (++st == NSTAGE) { st = 0; ph_par ^= 1; }
        }

        // denominator: reduce across the 8 jc lanes sharing each row group
#pragma unroll
        for (int d = 1; d < 8; d <<= 1)
#pragma unroll
            for (int g = 0; g < 8; g++)
                dacc[g] += __shfl_xor_sync(0xffffffffu, dacc[g], d);
        if (jc == 0) {
#pragma unroll
            for (int g = 0; g < 8; g++)
                g_den[js][i0 + pw * 32 + g * 4 + rsub] = dacc[g];
        }
    } else {
        // ------------------------- consumers (warps 0-3) -------------------
        // 64M x 64N warp tiles: 32 ldmatrix per tile (was 40)
        const int mrow0 = (w & 1) * 64;
        const int ncol0 = (w >> 1) * 64;
        int ph_par = 0;

        float acc[4][8][4];     // [m16][n8][frag]
#pragma unroll
        for (int mt = 0; mt < 4; mt++)
#pragma unroll
            for (int nt = 0; nt < 8; nt++)
#pragma unroll
                for (int u = 0; u < 4; u++) acc[mt][nt][u] = 0.0f;

        for (int tile = 0; tile < JTILES; ++tile) {
            mbar_wait(sb + SM_MB + st * 8, ph_par);

            const uint32_t ph = sb + st * ST_SZ + OFF_PH;
            const uint32_t bh = sb + st * ST_SZ + OFF_BH;

#pragma unroll
            for (int ks = 0; ks < 4; ks++) {
                uint32_t A[4][4];
#pragma unroll
                for (int mt = 0; mt < 4; mt++)
                    ldm_x4(A[mt], a_addr(ph, mrow0 + mt * 16, ks, lane));
#pragma unroll
                for (int nt = 0; nt < 4; nt++) {
                    uint32_t Bf[4];
                    ldm_x4(Bf, b_addr(bh, ncol0 + nt * 16, ks, lane));
#pragma unroll
                    for (int mt = 0; mt < 4; mt++) {
                        mma16816(acc[mt][2 * nt],     A[mt], Bf[0], Bf[1]);
                        mma16816(acc[mt][2 * nt + 1], A[mt], Bf[2], Bf[3]);
                    }
                }
            }

            mbar_arrive(sb + SM_MB + (NSTAGE + st) * 8);  // empty[st]
            if (++st == NSTAGE) { st = 0; ph_par ^= 1; }
        }

        // numerator writeout: 64 rows x 64 cols per warp
        float* numo = g_num[js];
#pragma unroll
        for (int mt = 0; mt < 4; mt++) {
            const int row = i0 + mrow0 + mt * 16 + (lane >> 2);
#pragma unroll
            for (int nt = 0; nt < 8; nt++) {
                const int col = ncol0 + nt * 8 + (lane & 3) * 2;
                *(float2*)(numo + (size_t)row * FDIM + col) =
                    make_float2(acc[mt][nt][0], acc[mt][nt][1]);
                *(float2*)(numo + (size_t)(row + 8) * FDIM + col) =
                    make_float2(acc[mt][nt][2], acc[mt][nt][3]);
            }
        }
    }
}

// ---------------------------------------------------------------------------
// Kernel 3: out = (num0+num1) / (den0+den1), float4-vectorized
// ---------------------------------------------------------------------------
__global__ void k_combine(float* __restrict__ out) {
    int idx  = blockIdx.x * 256 + threadIdx.x;
    int base = idx * 4;
    int i    = base >> 7;
    float inv = __frcp_rn(g_den[0][i] + g_den[1][i]);
    float4 n0 = *(const float4*)&g_num[0][base];
    float4 n1 = *(const float4*)&g_num[1][base];
    float4 o;
    o.x = (n0.x + n1.x) * inv;
    o.y = (n0.y + n1.y) * inv;
    o.z = (n0.z + n1.z) * inv;
    o.w = (n0.w + n1.w) * inv;
    *(float4*)&out[base] = o;
}

// ---------------------------------------------------------------------------
extern "C" void kernel_launch(void* const* d_in, const int* in_sizes, int n_in,
                              void* d_out, int out_size) {
    const float* inp = (const float*)d_in[0];
    const int*   adj = (const int*)d_in[1];
    const float* W   = (const float*)d_in[2];
    const float* a   = (const float*)d_in[3];
    float* out = (float*)d_out;

    cudaFuncSetAttribute(k_prep, cudaFuncAttributeMaxDynamicSharedMemorySize, PREP_SMEM);
    cudaFuncSetAttribute(k_attn, cudaFuncAttributeMaxDynamicSharedMemorySize, ATTN_SMEM);

    k_prep<<<NROWS / PBM, 512, PREP_SMEM>>>(inp, W, a);
    k_attn<<<dim3(NROWS / BM, JSPLIT, 1), 256, ATTN_SMEM>>>(adj);
    k_combine<<<(NROWS * FDIM) / 1024, 256>>>(out);
}

// round 16
// speedup vs baseline: 1.0634x; 1.0004x over previous
#include <cuda_runtime.h>
#include <cuda_fp16.h>
#include <cstdint>

// ---------------------------------------------------------------------------
// GAT layer, sm_103 base ISA. Warp-specialized producer/consumer (R8 skeleton)
// Round 16: adj staging pitch 256 -> 272 bytes.
//   bank(p*272 + q*16) = 4(p+q) mod 32  -> cp.async STS conflict-free
//   (was 8-way: bank(p*256+q*16) = 4q, p invisible mod 32).
// Keeps R15: consumer 64Mx64N tiles (32 ldm/tile), separable-exp producer,
// JSPLIT=2, 128 CTAs, 3-stage P/B ring, direct writeout.
// ---------------------------------------------------------------------------

#define NROWS 8192
#define FDIM  128
#define BM    128
#define BN    64
#define JSPLIT 2
#define JTILES ((NROWS / JSPLIT) / BN)   // 64
#define SHIFT 7.0f
#define NSTAGE 3
#define ADJ_PITCH 272
#define ADJ_BUF   (128 * ADJ_PITCH)      // 34816

// ---- scratch (device globals; no allocation allowed) ----
__device__ float  g_e1 [NROWS];    // exp(s1 - SHIFT)
__device__ float  g_e1s[NROWS];    // exp(0.01*s1 - SHIFT)
__device__ float  g_t1 [NROWS];    // exp(-s1)
__device__ float  g_e2 [NROWS];    // exp(s2)
__device__ float  g_e2s[NROWS];    // exp(0.01*s2)
__device__ __half g_hT_hi[(size_t)FDIM * NROWS];   // [c][j]
__device__ float  g_num[JSPLIT][(size_t)NROWS * FDIM];
__device__ float  g_den[JSPLIT][NROWS];

// ---------------------------------------------------------------------------
static __device__ __forceinline__ uint32_t smem_u32(const void* p) {
    uint32_t a;
    asm("{ .reg .u64 t; cvta.to.shared.u64 t, %1; cvt.u32.u64 %0, t; }"
        : "=r"(a) : "l"(p));
    return a;
}

static __device__ __forceinline__ void ldm_x4(uint32_t* r, uint32_t addr) {
    asm volatile("ldmatrix.sync.aligned.m8n8.x4.shared.b16 {%0,%1,%2,%3}, [%4];"
                 : "=r"(r[0]), "=r"(r[1]), "=r"(r[2]), "=r"(r[3]) : "r"(addr));
}

static __device__ __forceinline__ void mma16816(float* d, const uint32_t* a,
                                                uint32_t b0, uint32_t b1) {
    asm volatile(
        "mma.sync.aligned.m16n8k16.row.col.f32.f16.f16.f32 "
        "{%0,%1,%2,%3}, {%4,%5,%6,%7}, {%8,%9}, {%0,%1,%2,%3};"
        : "+f"(d[0]), "+f"(d[1]), "+f"(d[2]), "+f"(d[3])
        : "r"(a[0]), "r"(a[1]), "r"(a[2]), "r"(a[3]), "r"(b0), "r"(b1));
}

static __device__ __forceinline__ uint32_t pack_h2f(float lo, float hi) {
    uint32_t r;
    asm("cvt.rn.f16x2.f32 %0, %1, %2;" : "=r"(r) : "f"(hi), "f"(lo));
    return r;
}

// A-operand ldmatrix address: tile m16k16 at (m0, ks), 128B rows, chunk-XOR swizzle
static __device__ __forceinline__ uint32_t a_addr(uint32_t base, int m0, int ks, int lane) {
    int q = lane >> 3, row = lane & 7;
    int rr = m0 + ((q & 1) << 3) + row;
    int kc = ks * 2 + (q >> 1);
    return base + rr * 128 + ((kc ^ (rr & 7)) << 4);
}
// B-operand ldmatrix address: tile n16k16 at (n0, ks); B stored [n][k] rows
static __device__ __forceinline__ uint32_t b_addr(uint32_t base, int n0, int ks, int lane) {
    int q = lane >> 3, row = lane & 7;
    int nn = n0 + ((q >> 1) << 3) + row;
    int kc = ks * 2 + (q & 1);
    return base + nn * 128 + ((kc ^ (nn & 7)) << 4);
}

static __device__ __forceinline__ void mbar_init(uint32_t m, uint32_t cnt) {
    asm volatile("mbarrier.init.shared.b64 [%0], %1;" :: "r"(m), "r"(cnt) : "memory");
}
static __device__ __forceinline__ void mbar_arrive(uint32_t m) {
    asm volatile("mbarrier.arrive.shared.b64 _, [%0];" :: "r"(m) : "memory");
}
static __device__ __forceinline__ void mbar_wait(uint32_t m, uint32_t parity) {
    uint32_t done;
    asm volatile(
        "{\n\t.reg .pred p;\n\t"
        "mbarrier.try_wait.parity.acquire.cta.shared::cta.b64 p, [%1], %2;\n\t"
        "selp.b32 %0, 1, 0, p;\n\t}"
        : "=r"(done) : "r"(m), "r"(parity) : "memory");
    if (!done) {
        asm volatile(
            "{\n\t.reg .pred P1;\n\t"
            "WL_%=:\n\t"
            "mbarrier.try_wait.parity.acquire.cta.shared::cta.b64 P1, [%0], %1, 0x989680;\n\t"
            "@P1 bra.uni WD_%=;\n\t"
            "bra.uni WL_%=;\n\t"
            "WD_%=:\n\t}"
            :: "r"(m), "r"(parity) : "memory");
    }
}

static __device__ __forceinline__ void cp_async16(uint32_t dst, const void* src) {
    asm volatile("cp.async.cg.shared.global [%0], [%1], 16;"
                 :: "r"(dst), "l"(src) : "memory");
}
static __device__ __forceinline__ void cp_commit()  { asm volatile("cp.async.commit_group;" ::: "memory"); }
static __device__ __forceinline__ void cp_wait0()   { asm volatile("cp.async.wait_group 0;" ::: "memory"); }
static __device__ __forceinline__ void cp_wait1()   { asm volatile("cp.async.wait_group 1;" ::: "memory"); }
static __device__ __forceinline__ void cp_wait2()   { asm volatile("cp.async.wait_group 2;" ::: "memory"); }

// ---------------------------------------------------------------------------
// Kernel 1: h = X@W ; exp-separated softmax tables ; transposed fp16 h
// ---------------------------------------------------------------------------
#define PBM 64
#define HS_PITCH 133
#define PREP_SMEM ((16384 + PBM * HS_PITCH) * 4)

__global__ __launch_bounds__(512, 1)
void k_prep(const float* __restrict__ inp, const float* __restrict__ W,
            const float* __restrict__ a) {
    extern __shared__ float smf[];
    float* Ws = smf;                    // [k=128][c=128], natural layout
    float* hs = smf + 16384;            // [64][HS_PITCH]

    const int t  = threadIdx.x;
    const int i0 = blockIdx.x * PBM;

    for (int idx = t; idx < 16384; idx += 512) Ws[idx] = W[idx];
    __syncthreads();

    const int c4 = t & 31;    // column group (lane)
    const int rb = t >> 5;    // row block (uniform per warp)
    const float* irow = inp + (size_t)(i0 + rb * 4) * FDIM;

    float acc[4][4];
#pragma unroll
    for (int r = 0; r < 4; r++)
#pragma unroll
        for (int cc = 0; cc < 4; cc++) acc[r][cc] = 0.0f;

    for (int k4 = 0; k4 < 32; k4++) {
        float4 iv[4];
#pragma unroll
        for (int r = 0; r < 4; r++)
            iv[r] = *(const float4*)&irow[r * FDIM + k4 * 4];
        float4 wv[4];
#pragma unroll
        for (int kk = 0; kk < 4; kk++)
            wv[kk] = *(const float4*)&Ws[(k4 * 4 + kk) * 128 + c4 * 4];
#pragma unroll
        for (int r = 0; r < 4; r++) {
            float4 v = iv[r];
            acc[r][0] = fmaf(v.x, wv[0].x, fmaf(v.y, wv[1].x,
                        fmaf(v.z, wv[2].x, fmaf(v.w, wv[3].x, acc[r][0]))));
            acc[r][1] = fmaf(v.x, wv[0].y, fmaf(v.y, wv[1].y,
                        fmaf(v.z, wv[2].y, fmaf(v.w, wv[3].y, acc[r][1]))));
            acc[r][2] = fmaf(v.x, wv[0].z, fmaf(v.y, wv[1].z,
                        fmaf(v.z, wv[2].z, fmaf(v.w, wv[3].z, acc[r][2]))));
            acc[r][3] = fmaf(v.x, wv[0].w, fmaf(v.y, wv[1].w,
                        fmaf(v.z, wv[2].w, fmaf(v.w, wv[3].w, acc[r][3]))));
        }
    }
#pragma unroll
    for (int r = 0; r < 4; r++)
#pragma unroll
        for (int cc = 0; cc < 4; cc++)
            hs[(rb * 4 + r) * HS_PITCH + c4 * 4 + cc] = acc[r][cc];
    __syncthreads();

    if (t < PBM) {
        float s1 = 0.0f, s2 = 0.0f;
        for (int cc = 0; cc < 128; cc++) {
            float hv = hs[t * HS_PITCH + cc];
            s1 += hv * a[cc];
            s2 += hv * a[128 + cc];
        }
        const int gi = i0 + t;
        g_e1 [gi] = __expf(s1 - SHIFT);
        g_e1s[gi] = __expf(0.01f * s1 - SHIFT);
        g_t1 [gi] = __expf(-s1);
        g_e2 [gi] = __expf(s2);
        g_e2s[gi] = __expf(0.01f * s2);
    }

    const int ii = t & 63;
    const int c0 = t >> 6;    // 0..7
    for (int cc = c0; cc < 128; cc += 8)
        g_hT_hi[(size_t)cc * NROWS + i0 + ii] =
            __float2half_rn(hs[ii * HS_PITCH + cc]);
}

// ---------------------------------------------------------------------------
// Kernel 2: warp-specialized fused masked-softmax + P@h  (R8 skeleton)
// smem: 3 stages x { Ph 16KB | Bh 16KB } + 2 x 34KB adj (272B pitch) + mbars
// ---------------------------------------------------------------------------
#define ST_SZ   32768u
#define OFF_PH  0u
#define OFF_BH  16384u
#define SM_ADJ  98304u            // 2 x ADJ_BUF, row p at p*272
#define SM_MB   (98304u + 2u * ADJ_BUF)   // 167936
#define ATTN_SMEM (SM_MB + 64u)           // 168000

__global__ __launch_bounds__(256, 1)
void k_attn(const int* __restrict__ adj) {
    extern __shared__ char smem[];
    const uint32_t sb = smem_u32(smem);

    const int t    = threadIdx.x;
    const int lane = t & 31;
    const int w    = t >> 5;
    const int i0   = blockIdx.x * BM;
    const int js   = blockIdx.y;
    const int jbeg = js * (NROWS / JSPLIT);

    if (t == 0) {
#pragma unroll
        for (int s = 0; s < NSTAGE; s++) {
            mbar_init(sb + SM_MB + s * 8, 128);               // full[s]
            mbar_init(sb + SM_MB + (NSTAGE + s) * 8, 128);    // empty[s]
        }
    }
    __syncthreads();

    int st = 0;

    if (w >= 4) {
        // ------------------------- producers (warps 4-7) -------------------
        const int p    = t - 128;       // 0..127
        const int pw   = w - 4;
        const int rsub = lane >> 3;     // 0..3 : row-in-group
        const int jc   = lane & 7;      // 0..7 : 16B chunk within row
        int ph_par = 1;

        const int*   myrow = adj + (size_t)(i0 + p) * NROWS + jbeg;
        const uint32_t adst = sb + SM_ADJ + p * ADJ_PITCH;

        float dacc[8];
#pragma unroll
        for (int g = 0; g < 8; g++) dacc[g] = 0.0f;

        // per-row constants (exp-separated softmax tables), fixed i0 per CTA
        float Av[8], As[8], Tv[8];
#pragma unroll
        for (int g = 0; g < 8; g++) {
            const int ri = i0 + pw * 32 + g * 4 + rsub;
            Av[g] = g_e1[ri];
            As[g] = g_e1s[ri];
            Tv[g] = g_t1[ri];
        }

        // preload adj tile 0 into adj buffer 0
#pragma unroll
        for (int q = 0; q < 16; q++)
            cp_async16(adst + q * 16, myrow + q * 4);
        cp_commit();                                   // group A0

        for (int tile = 0; tile < JTILES; ++tile) {
            const int j0 = jbeg + tile * BN;
            mbar_wait(sb + SM_MB + (NSTAGE + st) * 8, ph_par);

            // async-load B tile (h^T fp16), swizzled
            const uint32_t bh = sb + st * ST_SZ + OFF_BH;
#pragma unroll
            for (int cc = 0; cc < 8; cc++) {
                const int cr = pw * 32 + cc * 4 + rsub;
                const uint32_t dst = cr * 128 + ((jc ^ (cr & 7)) << 4);
                cp_async16(bh + dst,
                           (const char*)g_hT_hi + ((size_t)cr * NROWS + j0 + jc * 8) * 2);
            }
            cp_commit();                               // group B_t

            // prefetch adj tile t+1 into the other adj buffer
            const int last = (tile == JTILES - 1);
            if (!last) {
                const int* src = myrow + (tile + 1) * BN;
                const uint32_t d2 = adst + (((tile + 1) & 1) * ADJ_BUF);
#pragma unroll
                for (int q = 0; q < 16; q++)
                    cp_async16(d2 + q * 16, src + q * 4);
                cp_commit();                           // group A_{t+1}
            }

            // wait for adj(t):  pending = [A_t, B_t, (A_{t+1})]
            if (!last) cp_wait2(); else cp_wait1();

            // compute P tile (fp16, swizzled) from smem adj — separable exp
            char* phb = smem + st * ST_SZ + OFF_PH;
            const char* ab = smem + SM_ADJ + (tile & 1) * ADJ_BUF;

            const float4* e2p  = (const float4*)(g_e2  + j0 + jc * 8);
            const float4* e2sp = (const float4*)(g_e2s + j0 + jc * 8);
            const float4 B0 = e2p[0],  B1 = e2p[1];
            const float4 C0 = e2sp[0], C1 = e2sp[1];
            const float Bv[8] = {B0.x, B0.y, B0.z, B0.w, B1.x, B1.y, B1.z, B1.w};
            const float Bs[8] = {C0.x, C0.y, C0.z, C0.w, C1.x, C1.y, C1.z, C1.w};

#pragma unroll
            for (int g = 0; g < 8; g++) {
                const int r = pw * 32 + g * 4 + rsub;
                const int4 A0 = *(const int4*)(ab + r * ADJ_PITCH + jc * 32);
                const int4 A1 = *(const int4*)(ab + r * ADJ_PITCH + jc * 32 + 16);
                const int av[8] = {A0.x, A0.y, A0.z, A0.w, A1.x, A1.y, A1.z, A1.w};
                const float Ag = Av[g], Asg = As[g], Tg = Tv[g];
                float pv[8];
#pragma unroll
                for (int u = 0; u < 8; u++) {
                    const bool pos = Bv[u] > Tg;           // s1+s2 >= 0 ?
                    float sa  = pos ? Ag : Asg;
                    float sbv = pos ? Bv[u] : Bs[u];
                    float v = sa * sbv;
                    v = (av[u] > 0) ? v : 0.0f;
                    dacc[g] += v;
                    pv[u] = v;
                }
                uint4 HH = make_uint4(pack_h2f(pv[0], pv[1]), pack_h2f(pv[2], pv[3]),
                                      pack_h2f(pv[4], pv[5]), pack_h2f(pv[6], pv[7]));
                *(uint4*)(phb + r * 128 + ((jc ^ (r & 7)) << 4)) = HH;
            }

            // wait for Bh(t), leave adj(t+1) in flight
            if (!last) cp_wait1(); else cp_wait0();
            mbar_arrive(sb + SM_MB + st * 8);   // full[st]

            if (++st == NSTAGE) { st = 0; ph_par ^= 1; }
        }

        // denominator: reduce across the 8 jc lanes sharing each row group
#pragma unroll
        for (int d = 1; d < 8; d <<= 1)
#pragma unroll
            for (int g = 0; g < 8; g++)
                dacc[g] += __shfl_xor_sync(0xffffffffu, dacc[g], d);
        if (jc == 0) {
#pragma unroll
            for (int g = 0; g < 8; g++)
                g_den[js][i0 + pw * 32 + g * 4 + rsub] = dacc[g];
        }
    } else {
        // ------------------------- consumers (warps 0-3) -------------------
        // 64M x 64N warp tiles: 32 ldmatrix per tile
        const int mrow0 = (w & 1) * 64;
        const int ncol0 = (w >> 1) * 64;
        int ph_par = 0;

        float acc[4][8][4];     // [m16][n8][frag]
#pragma unroll
        for (int mt = 0; mt < 4; mt++)
#pragma unroll
            for (int nt = 0; nt < 8; nt++)
#pragma unroll
                for (int u = 0; u < 4; u++) acc[mt][nt][u] = 0.0f;

        for (int tile = 0; tile < JTILES; ++tile) {
            mbar_wait(sb + SM_MB + st * 8, ph_par);

            const uint32_t ph = sb + st * ST_SZ + OFF_PH;
            const uint32_t bh = sb + st * ST_SZ + OFF_BH;

#pragma unroll
            for (int ks = 0; ks < 4; ks++) {
                uint32_t A[4][4];
#pragma unroll
                for (int mt = 0; mt < 4; mt++)
                    ldm_x4(A[mt], a_addr(ph, mrow0 + mt * 16, ks, lane));
#pragma unroll
                for (int nt = 0; nt < 4; nt++) {
                    uint32_t Bf[4];
                    ldm_x4(Bf, b_addr(bh, ncol0 + nt * 16, ks, lane));
#pragma unroll
                    for (int mt = 0; mt < 4; mt++) {
                        mma16816(acc[mt][2 * nt],     A[mt], Bf[0], Bf[1]);
                        mma16816(acc[mt][2 * nt + 1], A[mt], Bf[2], Bf[3]);
                    }
                }
            }

            mbar_arrive(sb + SM_MB + (NSTAGE + st) * 8);  // empty[st]
            if (++st == NSTAGE) { st = 0; ph_par ^= 1; }
        }

        // numerator writeout: 64 rows x 64 cols per warp
        float* numo = g_num[js];
#pragma unroll
        for (int mt = 0; mt < 4; mt++) {
            const int row = i0 + mrow0 + mt * 16 + (lane >> 2);
#pragma unroll
            for (int nt = 0; nt < 8; nt++) {
                const int col = ncol0 + nt * 8 + (lane & 3) * 2;
                *(float2*)(numo + (size_t)row * FDIM + col) =
                    make_float2(acc[mt][nt][0], acc[mt][nt][1]);
                *(float2*)(numo + (size_t)(row + 8) * FDIM + col) =
                    make_float2(acc[mt][nt][2], acc[mt][nt][3]);
            }
        }
    }
}

// ---------------------------------------------------------------------------
// Kernel 3: out = (num0+num1) / (den0+den1), float4-vectorized
// ---------------------------------------------------------------------------
__global__ void k_combine(float* __restrict__ out) {
    int idx  = blockIdx.x * 256 + threadIdx.x;
    int base = idx * 4;
    int i    = base >> 7;
    float inv = __frcp_rn(g_den[0][i] + g_den[1][i]);
    float4 n0 = *(const float4*)&g_num[0][base];
    float4 n1 = *(const float4*)&g_num[1][base];
    float4 o;
    o.x = (n0.x + n1.x) * inv;
    o.y = (n0.y + n1.y) * inv;
    o.z = (n0.z + n1.z) * inv;
    o.w = (n0.w + n1.w) * inv;
    *(float4*)&out[base] = o;
}

// ---------------------------------------------------------------------------
extern "C" void kernel_launch(void* const* d_in, const int* in_sizes, int n_in,
                              void* d_out, int out_size) {
    const float* inp = (const float*)d_in[0];
    const int*   adj = (const int*)d_in[1];
    const float* W   = (const float*)d_in[2];
    const float* a   = (const float*)d_in[3];
    float* out = (float*)d_out;

    cudaFuncSetAttribute(k_prep, cudaFuncAttributeMaxDynamicSharedMemorySize, PREP_SMEM);
    cudaFuncSetAttribute(k_attn, cudaFuncAttributeMaxDynamicSharedMemorySize, ATTN_SMEM);

    k_prep<<<NROWS / PBM, 512, PREP_SMEM>>>(inp, W, a);
    k_attn<<<dim3(NROWS / BM, JSPLIT, 1), 256, ATTN_SMEM>>>(adj);
    k_combine<<<(NROWS * FDIM) / 1024, 256>>>(out);
}